// round 4
// baseline (speedup 1.0000x reference)
#include <cuda_runtime.h>
#include <cstdint>
#include <cstdio>

#define EPS_LN 1e-5f

// segment-max accumulator as monotone-ordered uint keys; 0 == "never touched"
__device__ unsigned int g_agg[(size_t)50000 * 128];
__device__ int g_is64;

__device__ __forceinline__ unsigned floatToKey(float f) {
    unsigned u = __float_as_uint(f);
    return (u & 0x80000000u) ? ~u : (u | 0x80000000u);
}
__device__ __forceinline__ float keyToFloat(unsigned k) {
    if (k == 0u) return 0.0f;  // sentinel: node had no in-edges -> 0
    unsigned bits = (k & 0x80000000u) ? (k & 0x7fffffffu) : ~k;
    return __uint_as_float(bits);
}

__device__ __forceinline__ void sc_angle(float ax, float ay, float az,
                                         float bx, float by, float bz,
                                         float& s, float& c) {
    // sin/cos of atan2(||a x b||, a.b) without atan2/sincos
    float cx = ay * bz - az * by;
    float cy = az * bx - ax * bz;
    float cz = ax * by - ay * bx;
    float cn2 = cx * cx + cy * cy + cz * cz;
    float d = ax * bx + ay * by + az * bz;
    float den = cn2 + d * d;
    if (den > 0.0f) {
        float r = rsqrtf(den);
        s = sqrtf(cn2) * r;
        c = d * r;
    } else {  // atan2(0,0) = 0
        s = 0.0f;
        c = 1.0f;
    }
}

// ---------------------------------------------------------------------------
// Kernel 1: zero the agg key buffer + detect edge_index dtype (int64 vs int32)
// ---------------------------------------------------------------------------
__global__ void init_kernel(const int* __restrict__ ei32, size_t aggWords) {
    size_t tid = (size_t)blockIdx.x * blockDim.x + threadIdx.x;
    size_t stride = (size_t)gridDim.x * blockDim.x;
    uint4* p = (uint4*)g_agg;
    size_t n4 = aggWords >> 2;
    for (size_t i = tid; i < n4; i += stride) p[i] = make_uint4(0u, 0u, 0u, 0u);
    if (blockIdx.x == 0 && threadIdx.x == 0) {
        // if edge_index is int64 (values < 2^31), every odd 32-bit word is 0.
        int all0 = 1;
        for (int i = 0; i < 256; i++) all0 &= (ei32[2 * i + 1] == 0);
        g_is64 = all0;
    }
}

// ---------------------------------------------------------------------------
// Kernel 2: per-edge MLP (47->64->128, ReLU+LN each) + atomicMax scatter
// one warp processes 4 edges per iteration
// ---------------------------------------------------------------------------
__global__ __launch_bounds__(256)
void edge_kernel(const float* __restrict__ x, const float* __restrict__ pos,
                 const float* __restrict__ normal, const float* __restrict__ ea,
                 const void* __restrict__ eiPtr,
                 const float* __restrict__ W1, const float* __restrict__ b1,
                 const float* __restrict__ g1, const float* __restrict__ be1,
                 const float* __restrict__ W2, const float* __restrict__ b2,
                 const float* __restrict__ g2, const float* __restrict__ be2,
                 int E) {
    extern __shared__ float sm[];
    float* sW1t = sm;            // [64 rows][52 floats] (13 float4, conflict-free)
    float* sW2t = sm + 3328;     // [128 rows][68 floats] (17 float4)
    float* sb1  = sm + 12032;
    float* sg1  = sm + 12096;
    float* sbe1 = sm + 12160;
    float* sb2  = sm + 12224;
    float* sg2  = sm + 12352;
    float* sbe2 = sm + 12480;
    float* sIn  = sm + 12608;    // 8 warps * 4 edges * 48
    float* sH1  = sm + 14144;    // 8 warps * 4 edges * 64

    int tid = threadIdx.x;
    for (int t = tid; t < 47 * 64; t += 256) {
        int i = t / 64, k = t - i * 64;
        sW1t[k * 52 + i] = W1[t];
    }
    for (int k = tid; k < 64; k += 256) sW1t[k * 52 + 47] = 0.0f;
    for (int t = tid; t < 64 * 128; t += 256) {
        int i = t >> 7, k = t & 127;
        sW2t[k * 68 + i] = W2[t];
    }
    for (int t = tid; t < 64; t += 256) { sb1[t] = b1[t]; sg1[t] = g1[t]; sbe1[t] = be1[t]; }
    for (int t = tid; t < 128; t += 256) { sb2[t] = b2[t]; sg2[t] = g2[t]; sbe2[t] = be2[t]; }
    __syncthreads();

    const int lane = tid & 31;
    const int w = tid >> 5;
    const int warpGlobal = (blockIdx.x << 3) + w;
    const int warpsTotal = gridDim.x << 3;
    const bool is64 = (g_is64 != 0);
    const long long* ei64 = (const long long*)eiPtr;
    const int* ei32 = (const int*)eiPtr;

    float* myIn = sIn + w * (4 * 48);
    float* myH1 = sH1 + w * (4 * 64);

    // loop-invariant LN params for this lane
    const float ga = sg1[lane], gb = sg1[lane + 32];
    const float bea = sbe1[lane], beb = sbe1[lane + 32];
    float g2v[4], be2v[4], b2v[4];
    #pragma unroll
    for (int j = 0; j < 4; j++) {
        int k = lane + 32 * j;
        g2v[j] = sg2[k]; be2v[j] = sbe2[k]; b2v[j] = sb2[k];
    }
    const float bb0 = sb1[lane], bb1 = sb1[lane + 32];

    for (long long base = (long long)warpGlobal * 4; base < E;
         base += (long long)warpsTotal * 4) {
        int srcs[4], dsts[4];
        bool valid[4];
        #pragma unroll
        for (int m = 0; m < 4; m++) {
            long long e = base + m;
            valid[m] = (e < E);
            long long ec = valid[m] ? e : base;
            if (is64) {
                srcs[m] = (int)ei64[ec];
                dsts[m] = (int)ei64[(long long)E + ec];
            } else {
                srcs[m] = ei32[ec];
                dsts[m] = ei32[(long long)E + ec];
            }
        }
        // ---- stage 47-dim input into shared ----
        #pragma unroll
        for (int m = 0; m < 4; m++)
            myIn[m * 48 + lane] = x[(size_t)srcs[m] * 32 + lane];
        if (lane < 8) {
            #pragma unroll
            for (int m = 0; m < 4; m++) {
                long long ec = valid[m] ? (base + m) : base;
                myIn[m * 48 + 39 + lane] = ea[ec * 8 + lane];
            }
        }
        if (lane < 4) {
            int m = lane;
            int dI = dsts[m], sJ = srcs[m];
            float pix = pos[dI * 3 + 0], piy = pos[dI * 3 + 1], piz = pos[dI * 3 + 2];
            float pjx = pos[sJ * 3 + 0], pjy = pos[sJ * 3 + 1], pjz = pos[sJ * 3 + 2];
            float px = pjx - pix, py = pjy - piy, pz = pjz - piz;
            float nix = normal[dI * 3 + 0], niy = normal[dI * 3 + 1], niz = normal[dI * 3 + 2];
            float njx = normal[sJ * 3 + 0], njy = normal[sJ * 3 + 1], njz = normal[sJ * 3 + 2];
            float* q = myIn + m * 48;
            q[32] = sqrtf(px * px + py * py + pz * pz) * 0.125f;
            float s, c;
            sc_angle(nix, niy, niz, px, py, pz, s, c);  q[33] = s; q[34] = c;
            sc_angle(njx, njy, njz, px, py, pz, s, c);  q[35] = s; q[36] = c;
            sc_angle(nix, niy, niz, njx, njy, njz, s, c); q[37] = s; q[38] = c;
            q[47] = 0.0f;
        }
        __syncwarp();

        // ---- GEMV1: 48(pad)->64, lane owns cols {lane, lane+32} ----
        float a0[4], a1[4];
        #pragma unroll
        for (int m = 0; m < 4; m++) { a0[m] = bb0; a1[m] = bb1; }
        {
            const float4* wa4 = (const float4*)(sW1t + lane * 52);
            const float4* wb4 = (const float4*)(sW1t + (lane + 32) * 52);
            #pragma unroll 4
            for (int i4 = 0; i4 < 12; i4++) {
                float4 wa = wa4[i4], wb = wb4[i4];
                #pragma unroll
                for (int m = 0; m < 4; m++) {
                    float4 xm = ((const float4*)(myIn + m * 48))[i4];
                    a0[m] += xm.x * wa.x; a0[m] += xm.y * wa.y;
                    a0[m] += xm.z * wa.z; a0[m] += xm.w * wa.w;
                    a1[m] += xm.x * wb.x; a1[m] += xm.y * wb.y;
                    a1[m] += xm.z * wb.z; a1[m] += xm.w * wb.w;
                }
            }
        }
        // ReLU + LayerNorm(64)
        float sum[4], sq[4];
        #pragma unroll
        for (int m = 0; m < 4; m++) {
            a0[m] = fmaxf(a0[m], 0.0f);
            a1[m] = fmaxf(a1[m], 0.0f);
            sum[m] = a0[m] + a1[m];
            sq[m] = a0[m] * a0[m] + a1[m] * a1[m];
        }
        #pragma unroll
        for (int off = 16; off > 0; off >>= 1) {
            #pragma unroll
            for (int m = 0; m < 4; m++) {
                sum[m] += __shfl_xor_sync(0xffffffffu, sum[m], off);
                sq[m]  += __shfl_xor_sync(0xffffffffu, sq[m], off);
            }
        }
        #pragma unroll
        for (int m = 0; m < 4; m++) {
            float mu = sum[m] * (1.0f / 64.0f);
            float var = sq[m] * (1.0f / 64.0f) - mu * mu;
            float rs = rsqrtf(var + EPS_LN);
            myH1[m * 64 + lane]      = (a0[m] - mu) * rs * ga + bea;
            myH1[m * 64 + lane + 32] = (a1[m] - mu) * rs * gb + beb;
        }
        __syncwarp();

        // ---- GEMV2: 64->128, lane owns cols {lane+32j} ----
        float acc[4][4];  // [j][m]
        #pragma unroll
        for (int j = 0; j < 4; j++)
            #pragma unroll
            for (int m = 0; m < 4; m++) acc[j][m] = b2v[j];
        #pragma unroll 4
        for (int i4 = 0; i4 < 16; i4++) {
            float4 wv[4];
            #pragma unroll
            for (int j = 0; j < 4; j++)
                wv[j] = *(const float4*)(sW2t + (lane + 32 * j) * 68 + i4 * 4);
            #pragma unroll
            for (int m = 0; m < 4; m++) {
                float4 xm = ((const float4*)(myH1 + m * 64))[i4];
                #pragma unroll
                for (int j = 0; j < 4; j++) {
                    acc[j][m] += xm.x * wv[j].x; acc[j][m] += xm.y * wv[j].y;
                    acc[j][m] += xm.z * wv[j].z; acc[j][m] += xm.w * wv[j].w;
                }
            }
        }
        // ReLU + LayerNorm(128) + atomicMax scatter
        float sum2[4], sq2[4];
        #pragma unroll
        for (int m = 0; m < 4; m++) {
            sum2[m] = 0.0f; sq2[m] = 0.0f;
            #pragma unroll
            for (int j = 0; j < 4; j++) {
                float v = fmaxf(acc[j][m], 0.0f);
                acc[j][m] = v;
                sum2[m] += v;
                sq2[m] += v * v;
            }
        }
        #pragma unroll
        for (int off = 16; off > 0; off >>= 1) {
            #pragma unroll
            for (int m = 0; m < 4; m++) {
                sum2[m] += __shfl_xor_sync(0xffffffffu, sum2[m], off);
                sq2[m]  += __shfl_xor_sync(0xffffffffu, sq2[m], off);
            }
        }
        #pragma unroll
        for (int m = 0; m < 4; m++) {
            float mu = sum2[m] * (1.0f / 128.0f);
            float var = sq2[m] * (1.0f / 128.0f) - mu * mu;
            float rs = rsqrtf(var + EPS_LN);
            if (valid[m]) {
                size_t rowO = (size_t)dsts[m] * 128;
                #pragma unroll
                for (int j = 0; j < 4; j++) {
                    float msg = (acc[j][m] - mu) * rs * g2v[j] + be2v[j];
                    atomicMax(&g_agg[rowO + lane + 32 * j], floatToKey(msg));
                }
            }
        }
        __syncwarp();
    }
}

// ---------------------------------------------------------------------------
// Kernel 3: node MLP 128->256 (ReLU+LN), one warp x 4 nodes
// ---------------------------------------------------------------------------
__global__ __launch_bounds__(512)
void node_kernel(const float* __restrict__ Wg, const float* __restrict__ bg,
                 const float* __restrict__ gg, const float* __restrict__ beg,
                 float* __restrict__ out, int nNodes) {
    extern __shared__ float sm[];
    float* sWgT = sm;            // [256 rows][132 floats] (33 float4)
    float* sbg  = sm + 33792;
    float* sgg  = sm + 34048;
    float* sbeg = sm + 34304;
    float* sH   = sm + 34560;    // 16 warps * 4 nodes * 128

    int tid = threadIdx.x;
    for (int t = tid; t < 128 * 256; t += 512) {
        int i = t >> 8, k = t & 255;
        sWgT[k * 132 + i] = Wg[t];
    }
    for (int t = tid; t < 256; t += 512) { sbg[t] = bg[t]; sgg[t] = gg[t]; sbeg[t] = beg[t]; }
    __syncthreads();

    int lane = tid & 31, w = tid >> 5;
    int warpGlobal = blockIdx.x * 16 + w;
    int warpsTotal = gridDim.x * 16;
    float* myH = sH + w * 512;

    float bj[8], gj[8], bej[8];
    #pragma unroll
    for (int j = 0; j < 8; j++) {
        int k = lane + 32 * j;
        bj[j] = sbg[k]; gj[j] = sgg[k]; bej[j] = sbeg[k];
    }

    for (int base = warpGlobal * 4; base < nNodes; base += warpsTotal * 4) {
        #pragma unroll
        for (int m = 0; m < 4; m++) {
            int node = base + m;
            int nc = (node < nNodes) ? node : base;
            uint4 kv = ((const uint4*)g_agg)[(size_t)nc * 32 + lane];
            float4 f;
            f.x = keyToFloat(kv.x); f.y = keyToFloat(kv.y);
            f.z = keyToFloat(kv.z); f.w = keyToFloat(kv.w);
            ((float4*)(myH + m * 128))[lane] = f;
        }
        __syncwarp();

        float acc[8][4];  // [j][m]
        #pragma unroll
        for (int j = 0; j < 8; j++)
            #pragma unroll
            for (int m = 0; m < 4; m++) acc[j][m] = bj[j];

        #pragma unroll 4
        for (int i4 = 0; i4 < 32; i4++) {
            float4 wv[8];
            #pragma unroll
            for (int j = 0; j < 8; j++)
                wv[j] = *(const float4*)(sWgT + (lane + 32 * j) * 132 + i4 * 4);
            #pragma unroll
            for (int m = 0; m < 4; m++) {
                float4 xm = ((const float4*)(myH + m * 128))[i4];
                #pragma unroll
                for (int j = 0; j < 8; j++) {
                    acc[j][m] += xm.x * wv[j].x; acc[j][m] += xm.y * wv[j].y;
                    acc[j][m] += xm.z * wv[j].z; acc[j][m] += xm.w * wv[j].w;
                }
            }
        }

        float sum[4], sq[4];
        #pragma unroll
        for (int m = 0; m < 4; m++) {
            sum[m] = 0.0f; sq[m] = 0.0f;
            #pragma unroll
            for (int j = 0; j < 8; j++) {
                float v = fmaxf(acc[j][m], 0.0f);
                acc[j][m] = v;
                sum[m] += v;
                sq[m] += v * v;
            }
        }
        #pragma unroll
        for (int off = 16; off > 0; off >>= 1) {
            #pragma unroll
            for (int m = 0; m < 4; m++) {
                sum[m] += __shfl_xor_sync(0xffffffffu, sum[m], off);
                sq[m]  += __shfl_xor_sync(0xffffffffu, sq[m], off);
            }
        }
        #pragma unroll
        for (int m = 0; m < 4; m++) {
            int node = base + m;
            if (node < nNodes) {
                float mu = sum[m] * (1.0f / 256.0f);
                float var = sq[m] * (1.0f / 256.0f) - mu * mu;
                float rs = rsqrtf(var + EPS_LN);
                #pragma unroll
                for (int j = 0; j < 8; j++)
                    out[(size_t)node * 256 + lane + 32 * j] =
                        (acc[j][m] - mu) * rs * gj[j] + bej[j];
            }
        }
        __syncwarp();
    }
}

// ---------------------------------------------------------------------------
extern "C" void kernel_launch(void* const* d_in, const int* in_sizes, int n_in,
                              void* d_out, int out_size) {
    const float* x      = (const float*)d_in[0];
    const float* pos    = (const float*)d_in[1];
    const float* normal = (const float*)d_in[2];
    const float* ea     = (const float*)d_in[3];
    const void*  ei     = d_in[4];
    const float* W1  = (const float*)d_in[5];
    const float* b1  = (const float*)d_in[6];
    const float* g1  = (const float*)d_in[7];
    const float* be1 = (const float*)d_in[8];
    const float* W2  = (const float*)d_in[9];
    const float* b2  = (const float*)d_in[10];
    const float* g2  = (const float*)d_in[11];
    const float* be2 = (const float*)d_in[12];
    const float* Wg  = (const float*)d_in[13];
    const float* bg  = (const float*)d_in[14];
    const float* gg  = (const float*)d_in[15];
    const float* beg = (const float*)d_in[16];
    float* out = (float*)d_out;

    int E = in_sizes[4] / 2;
    int N = in_sizes[1] / 3;

    static const size_t edgeSmem = 16192 * sizeof(float);   // 64768 B
    static const size_t nodeSmem = 42752 * sizeof(float);   // 171008 B
    cudaFuncSetAttribute(edge_kernel, cudaFuncAttributeMaxDynamicSharedMemorySize,
                         (int)edgeSmem);
    cudaFuncSetAttribute(node_kernel, cudaFuncAttributeMaxDynamicSharedMemorySize,
                         (int)nodeSmem);

    init_kernel<<<592, 256>>>((const int*)ei, (size_t)N * 128);
    edge_kernel<<<444, 256, edgeSmem>>>(x, pos, normal, ea, ei,
                                        W1, b1, g1, be1, W2, b2, g2, be2, E);
    node_kernel<<<148, 512, nodeSmem>>>(Wg, bg, gg, beg, out, N);
}

// round 6
// speedup vs baseline: 1.1484x; 1.1484x over previous
#include <cuda_runtime.h>
#include <cstdint>
#include <cstdio>

#define EPS_LN 1e-5f
#define MAX_N 50048
#define MAX_E 1600064

__device__ float g_aggf[(size_t)50000 * 128];
__device__ int g_deg[MAX_N];
__device__ int g_cur[MAX_N];
__device__ int g_off[MAX_N + 1];
__device__ int g_csr[MAX_E];
__device__ int g_is64;

// ---------------------------------------------------------------------------
// packed f32x2 helpers (FFMA2)
// ---------------------------------------------------------------------------
__device__ __forceinline__ void ffma2(unsigned long long& d,
                                      unsigned long long a,
                                      unsigned long long b) {
    asm("fma.rn.f32x2 %0, %1, %2, %0;" : "+l"(d) : "l"(a), "l"(b));
}
__device__ __forceinline__ unsigned long long packf2(float lo, float hi) {
    return ((unsigned long long)__float_as_uint(hi) << 32) |
           (unsigned long long)__float_as_uint(lo);
}
__device__ __forceinline__ float f2sum(unsigned long long v) {
    return __uint_as_float((unsigned)v) + __uint_as_float((unsigned)(v >> 32));
}

__device__ __forceinline__ void sc_angle(float ax, float ay, float az,
                                         float bx, float by, float bz,
                                         float& s, float& c) {
    float cx = ay * bz - az * by;
    float cy = az * bx - ax * bz;
    float cz = ax * by - ay * bx;
    float cn2 = cx * cx + cy * cy + cz * cz;
    float d = ax * bx + ay * by + az * bz;
    float den = cn2 + d * d;
    if (den > 0.0f) {
        float r = rsqrtf(den);
        s = sqrtf(cn2) * r;
        c = d * r;
    } else {
        s = 0.0f;
        c = 1.0f;
    }
}

// ---------------------------------------------------------------------------
// Kernel 1: zero degree counters + detect edge_index dtype (int64 vs int32)
// ---------------------------------------------------------------------------
__global__ void init_kernel(const int* __restrict__ ei32, int nNodes) {
    int tid = blockIdx.x * blockDim.x + threadIdx.x;
    int stride = gridDim.x * blockDim.x;
    for (int i = tid; i < nNodes; i += stride) g_deg[i] = 0;
    if (blockIdx.x == 0 && threadIdx.x == 0) {
        int all0 = 1;
        for (int i = 0; i < 256; i++) all0 &= (ei32[2 * i + 1] == 0);
        g_is64 = all0;
    }
}

// ---------------------------------------------------------------------------
// Kernel 2: histogram of dst
// ---------------------------------------------------------------------------
__global__ void hist_kernel(const void* __restrict__ eiPtr, int E) {
    const bool is64 = (g_is64 != 0);
    const long long* ei64 = (const long long*)eiPtr;
    const int* ei32 = (const int*)eiPtr;
    int tid = blockIdx.x * blockDim.x + threadIdx.x;
    int stride = gridDim.x * blockDim.x;
    for (int e = tid; e < E; e += stride) {
        int dst = is64 ? (int)ei64[(long long)E + e] : ei32[(long long)E + e];
        atomicAdd(&g_deg[dst], 1);
    }
}

// ---------------------------------------------------------------------------
// Kernel 3: single-block exclusive scan -> g_off, copy to g_cur
// ---------------------------------------------------------------------------
__global__ void scan_kernel(int nNodes) {
    __shared__ int part[1024];
    int t = threadIdx.x;
    int CH = (nNodes + 1023) / 1024;
    int base = t * CH;
    int s = 0;
    for (int k = 0; k < CH; k++) {
        int idx = base + k;
        if (idx < nNodes) s += g_deg[idx];
    }
    part[t] = s;
    __syncthreads();
    for (int off = 1; off < 1024; off <<= 1) {
        int v = (t >= off) ? part[t - off] : 0;
        __syncthreads();
        part[t] += v;
        __syncthreads();
    }
    int run = part[t] - s;  // exclusive prefix for this chunk
    for (int k = 0; k < CH; k++) {
        int idx = base + k;
        if (idx < nNodes) {
            g_off[idx] = run;
            g_cur[idx] = run;
            run += g_deg[idx];
        }
    }
    if (t == 1023) g_off[nNodes] = run;
}

// ---------------------------------------------------------------------------
// Kernel 4: fill CSR with edge ids
// ---------------------------------------------------------------------------
__global__ void fill_kernel(const void* __restrict__ eiPtr, int E) {
    const bool is64 = (g_is64 != 0);
    const long long* ei64 = (const long long*)eiPtr;
    const int* ei32 = (const int*)eiPtr;
    int tid = blockIdx.x * blockDim.x + threadIdx.x;
    int stride = gridDim.x * blockDim.x;
    for (int e = tid; e < E; e += stride) {
        int dst = is64 ? (int)ei64[(long long)E + e] : ei32[(long long)E + e];
        int p = atomicAdd(&g_cur[dst], 1);
        g_csr[p] = e;
    }
}

// ---------------------------------------------------------------------------
// Kernel 5: node-centric edge MLP (47->64->128, ReLU+LN each) + register max.
// One warp per node; 8 in-edges per iteration; packed f32x2 FMA throughout.
// ---------------------------------------------------------------------------
__global__ __launch_bounds__(256)
void compute_kernel(const float* __restrict__ x, const float* __restrict__ pos,
                    const float* __restrict__ normal, const float* __restrict__ ea,
                    const void* __restrict__ eiPtr,
                    const float* __restrict__ W1, const float* __restrict__ b1,
                    const float* __restrict__ g1, const float* __restrict__ be1,
                    const float* __restrict__ W2, const float* __restrict__ b2,
                    const float* __restrict__ g2, const float* __restrict__ be2,
                    int E, int nNodes) {
    extern __shared__ float sm[];
    float* sW1t = sm;            // [64 rows][52 floats]
    float* sW2t = sm + 3328;     // [128 rows][68 floats]
    float* sb1  = sm + 12032;
    float* sg1  = sm + 12096;
    float* sbe1 = sm + 12160;
    float* sb2  = sm + 12224;
    float* sg2  = sm + 12352;
    float* sbe2 = sm + 12480;
    float* sIn  = sm + 12608;    // 8 warps * 8 edges * 48
    float* sH1  = sm + 15680;    // 8 warps * 8 edges * 64

    int tid = threadIdx.x;
    for (int t = tid; t < 47 * 64; t += 256) {
        int i = t / 64, k = t - i * 64;
        sW1t[k * 52 + i] = W1[t];
    }
    for (int k = tid; k < 64; k += 256) sW1t[k * 52 + 47] = 0.0f;
    for (int t = tid; t < 64 * 128; t += 256) {
        int i = t >> 7, k = t & 127;
        sW2t[k * 68 + i] = W2[t];
    }
    for (int t = tid; t < 64; t += 256) { sb1[t] = b1[t]; sg1[t] = g1[t]; sbe1[t] = be1[t]; }
    for (int t = tid; t < 128; t += 256) { sb2[t] = b2[t]; sg2[t] = g2[t]; sbe2[t] = be2[t]; }
    __syncthreads();

    const int lane = tid & 31;
    const int w = tid >> 5;
    const int warpGlobal = (blockIdx.x << 3) + w;
    const int warpsTotal = gridDim.x << 3;
    const bool is64 = (g_is64 != 0);
    const long long* ei64 = (const long long*)eiPtr;
    const int* ei32 = (const int*)eiPtr;

    float* myIn = sIn + w * (8 * 48);
    float* myH1 = sH1 + w * (8 * 64);

    // loop-invariant params
    const float ga = sg1[lane], gb = sg1[lane + 32];
    const float bea = sbe1[lane], beb = sbe1[lane + 32];
    const float bb0 = sb1[lane], bb1 = sb1[lane + 32];
    float g2v[4], be2v[4], b2v[4];
    #pragma unroll
    for (int j = 0; j < 4; j++) {
        int k = lane + 32 * j;
        g2v[j] = sg2[k]; be2v[j] = sbe2[k]; b2v[j] = sb2[k];
    }
    const float NEG_INF = -__int_as_float(0x7f800000);

    for (int node = warpGlobal; node < nNodes; node += warpsTotal) {
        int rowStart = g_off[node];
        int deg = g_off[node + 1] - rowStart;

        float maxacc[4];
        #pragma unroll
        for (int j = 0; j < 4; j++) maxacc[j] = NEG_INF;

        // node-invariant geometry
        float pix = pos[node * 3 + 0], piy = pos[node * 3 + 1], piz = pos[node * 3 + 2];
        float nix = normal[node * 3 + 0], niy = normal[node * 3 + 1], niz = normal[node * 3 + 2];

        for (int it = 0; it < deg; it += 8) {
            int m8 = deg - it; if (m8 > 8) m8 = 8;
            int eid = 0, src = 0;
            if (lane < 8) {
                int idx = it + lane;
                int cl = (idx < deg) ? idx : it;
                eid = g_csr[rowStart + cl];
                src = is64 ? (int)ei64[eid] : ei32[eid];
            }
            int srcs[8];
            long long eids[8];
            #pragma unroll
            for (int m = 0; m < 8; m++) {
                srcs[m] = __shfl_sync(0xffffffffu, src, m);
                eids[m] = __shfl_sync(0xffffffffu, eid, m);
            }
            // stage x[src] rows (32 floats each)
            #pragma unroll
            for (int m = 0; m < 8; m++)
                myIn[m * 48 + lane] = x[(size_t)srcs[m] * 32 + lane];
            // stage edge_attr
            if (lane < 8) {
                #pragma unroll
                for (int m = 0; m < 8; m++)
                    myIn[m * 48 + 39 + lane] = ea[eids[m] * 8 + lane];
            }
            // ppf: lane m handles edge m
            if (lane < 8) {
                int sJ = src;
                float pjx = pos[sJ * 3 + 0], pjy = pos[sJ * 3 + 1], pjz = pos[sJ * 3 + 2];
                float px = pjx - pix, py = pjy - piy, pz = pjz - piz;
                float njx = normal[sJ * 3 + 0], njy = normal[sJ * 3 + 1], njz = normal[sJ * 3 + 2];
                float* q = myIn + lane * 48;
                q[32] = sqrtf(px * px + py * py + pz * pz) * 0.125f;
                float s, c;
                sc_angle(nix, niy, niz, px, py, pz, s, c);   q[33] = s; q[34] = c;
                sc_angle(njx, njy, njz, px, py, pz, s, c);   q[35] = s; q[36] = c;
                sc_angle(nix, niy, niz, njx, njy, njz, s, c); q[37] = s; q[38] = c;
                q[47] = 0.0f;
            }
            __syncwarp();

            // ---- GEMV1: 48(pad)->64 packed f32x2; lane owns cols {lane, lane+32}
            unsigned long long a0[8], a1[8];
            #pragma unroll
            for (int m = 0; m < 8; m++) {
                a0[m] = packf2(bb0, 0.0f);
                a1[m] = packf2(bb1, 0.0f);
            }
            {
                const ulonglong2* wa = (const ulonglong2*)(sW1t + lane * 52);
                const ulonglong2* wb = (const ulonglong2*)(sW1t + (lane + 32) * 52);
                #pragma unroll 3
                for (int i4 = 0; i4 < 12; i4++) {
                    ulonglong2 wav = wa[i4], wbv = wb[i4];
                    #pragma unroll
                    for (int m = 0; m < 8; m++) {
                        ulonglong2 xv = ((const ulonglong2*)(myIn + m * 48))[i4];
                        ffma2(a0[m], xv.x, wav.x);
                        ffma2(a0[m], xv.y, wav.y);
                        ffma2(a1[m], xv.x, wbv.x);
                        ffma2(a1[m], xv.y, wbv.y);
                    }
                }
            }
            // ReLU + LayerNorm(64)
            float sum[8], sq[8], a0f[8], a1f[8];
            #pragma unroll
            for (int m = 0; m < 8; m++) {
                a0f[m] = fmaxf(f2sum(a0[m]), 0.0f);
                a1f[m] = fmaxf(f2sum(a1[m]), 0.0f);
                sum[m] = a0f[m] + a1f[m];
                sq[m] = a0f[m] * a0f[m] + a1f[m] * a1f[m];
            }
            #pragma unroll
            for (int off = 16; off > 0; off >>= 1) {
                #pragma unroll
                for (int m = 0; m < 8; m++) {
                    sum[m] += __shfl_xor_sync(0xffffffffu, sum[m], off);
                    sq[m]  += __shfl_xor_sync(0xffffffffu, sq[m], off);
                }
            }
            #pragma unroll
            for (int m = 0; m < 8; m++) {
                float mu = sum[m] * (1.0f / 64.0f);
                float var = sq[m] * (1.0f / 64.0f) - mu * mu;
                float rs = rsqrtf(var + EPS_LN);
                myH1[m * 64 + lane]      = (a0f[m] - mu) * rs * ga + bea;
                myH1[m * 64 + lane + 32] = (a1f[m] - mu) * rs * gb + beb;
            }
            __syncwarp();

            // ---- GEMV2: 64->128 packed f32x2; lane owns cols {lane+32j}
            unsigned long long acc2[4][8];
            #pragma unroll
            for (int j = 0; j < 4; j++)
                #pragma unroll
                for (int m = 0; m < 8; m++) acc2[j][m] = packf2(b2v[j], 0.0f);
            #pragma unroll 2
            for (int i4 = 0; i4 < 16; i4++) {
                ulonglong2 wv[4];
                #pragma unroll
                for (int j = 0; j < 4; j++)
                    wv[j] = *(const ulonglong2*)(sW2t + (lane + 32 * j) * 68 + i4 * 4);
                #pragma unroll
                for (int m = 0; m < 8; m++) {
                    ulonglong2 xv = ((const ulonglong2*)(myH1 + m * 64))[i4];
                    #pragma unroll
                    for (int j = 0; j < 4; j++) {
                        ffma2(acc2[j][m], xv.x, wv[j].x);
                        ffma2(acc2[j][m], xv.y, wv[j].y);
                    }
                }
            }
            // ReLU + LayerNorm(128) + register max
            float acc[4][8], sum2[8], sq2[8];
            #pragma unroll
            for (int m = 0; m < 8; m++) {
                sum2[m] = 0.0f; sq2[m] = 0.0f;
                #pragma unroll
                for (int j = 0; j < 4; j++) {
                    float v = fmaxf(f2sum(acc2[j][m]), 0.0f);
                    acc[j][m] = v;
                    sum2[m] += v;
                    sq2[m] += v * v;
                }
            }
            #pragma unroll
            for (int off = 16; off > 0; off >>= 1) {
                #pragma unroll
                for (int m = 0; m < 8; m++) {
                    sum2[m] += __shfl_xor_sync(0xffffffffu, sum2[m], off);
                    sq2[m]  += __shfl_xor_sync(0xffffffffu, sq2[m], off);
                }
            }
            #pragma unroll
            for (int m = 0; m < 8; m++) {
                float mu = sum2[m] * (1.0f / 128.0f);
                float var = sq2[m] * (1.0f / 128.0f) - mu * mu;
                float rs = rsqrtf(var + EPS_LN);
                if (m < m8) {
                    #pragma unroll
                    for (int j = 0; j < 4; j++) {
                        float msg = (acc[j][m] - mu) * rs * g2v[j] + be2v[j];
                        maxacc[j] = fmaxf(maxacc[j], msg);
                    }
                }
            }
            __syncwarp();
        }

        // write aggregated features (0 for isolated nodes)
        #pragma unroll
        for (int j = 0; j < 4; j++)
            g_aggf[(size_t)node * 128 + lane + 32 * j] = (deg > 0) ? maxacc[j] : 0.0f;
    }
}

// ---------------------------------------------------------------------------
// Kernel 6: node MLP 128->256 (ReLU+LN), one warp x 4 nodes
// ---------------------------------------------------------------------------
__global__ __launch_bounds__(512)
void node_kernel(const float* __restrict__ Wg, const float* __restrict__ bg,
                 const float* __restrict__ gg, const float* __restrict__ beg,
                 float* __restrict__ out, int nNodes) {
    extern __shared__ float sm[];
    float* sWgT = sm;            // [256 rows][132 floats]
    float* sbg  = sm + 33792;
    float* sgg  = sm + 34048;
    float* sbeg = sm + 34304;
    float* sH   = sm + 34560;    // 16 warps * 4 nodes * 128

    int tid = threadIdx.x;
    for (int t = tid; t < 128 * 256; t += 512) {
        int i = t >> 8, k = t & 255;
        sWgT[k * 132 + i] = Wg[t];
    }
    for (int t = tid; t < 256; t += 512) { sbg[t] = bg[t]; sgg[t] = gg[t]; sbeg[t] = beg[t]; }
    __syncthreads();

    int lane = tid & 31, w = tid >> 5;
    int warpGlobal = blockIdx.x * 16 + w;
    int warpsTotal = gridDim.x * 16;
    float* myH = sH + w * 512;

    float bj[8], gj[8], bej[8];
    #pragma unroll
    for (int j = 0; j < 8; j++) {
        int k = lane + 32 * j;
        bj[j] = sbg[k]; gj[j] = sgg[k]; bej[j] = sbeg[k];
    }

    for (int base = warpGlobal * 4; base < nNodes; base += warpsTotal * 4) {
        #pragma unroll
        for (int m = 0; m < 4; m++) {
            int node = base + m;
            int nc = (node < nNodes) ? node : base;
            float4 f = ((const float4*)g_aggf)[(size_t)nc * 32 + lane];
            ((float4*)(myH + m * 128))[lane] = f;
        }
        __syncwarp();

        float acc[8][4];  // [j][m]
        #pragma unroll
        for (int j = 0; j < 8; j++)
            #pragma unroll
            for (int m = 0; m < 4; m++) acc[j][m] = bj[j];

        #pragma unroll 4
        for (int i4 = 0; i4 < 32; i4++) {
            float4 wv[8];
            #pragma unroll
            for (int j = 0; j < 8; j++)
                wv[j] = *(const float4*)(sWgT + (lane + 32 * j) * 132 + i4 * 4);
            #pragma unroll
            for (int m = 0; m < 4; m++) {
                float4 xm = ((const float4*)(myH + m * 128))[i4];
                #pragma unroll
                for (int j = 0; j < 8; j++) {
                    acc[j][m] += xm.x * wv[j].x; acc[j][m] += xm.y * wv[j].y;
                    acc[j][m] += xm.z * wv[j].z; acc[j][m] += xm.w * wv[j].w;
                }
            }
        }

        float sum[4], sq[4];
        #pragma unroll
        for (int m = 0; m < 4; m++) {
            sum[m] = 0.0f; sq[m] = 0.0f;
            #pragma unroll
            for (int j = 0; j < 8; j++) {
                float v = fmaxf(acc[j][m], 0.0f);
                acc[j][m] = v;
                sum[m] += v;
                sq[m] += v * v;
            }
        }
        #pragma unroll
        for (int off = 16; off > 0; off >>= 1) {
            #pragma unroll
            for (int m = 0; m < 4; m++) {
                sum[m] += __shfl_xor_sync(0xffffffffu, sum[m], off);
                sq[m]  += __shfl_xor_sync(0xffffffffu, sq[m], off);
            }
        }
        #pragma unroll
        for (int m = 0; m < 4; m++) {
            int node = base + m;
            if (node < nNodes) {
                float mu = sum[m] * (1.0f / 256.0f);
                float var = sq[m] * (1.0f / 256.0f) - mu * mu;
                float rs = rsqrtf(var + EPS_LN);
                #pragma unroll
                for (int j = 0; j < 8; j++)
                    out[(size_t)node * 256 + lane + 32 * j] =
                        (acc[j][m] - mu) * rs * gj[j] + bej[j];
            }
        }
        __syncwarp();
    }
}

// ---------------------------------------------------------------------------
extern "C" void kernel_launch(void* const* d_in, const int* in_sizes, int n_in,
                              void* d_out, int out_size) {
    const float* x      = (const float*)d_in[0];
    const float* pos    = (const float*)d_in[1];
    const float* normal = (const float*)d_in[2];
    const float* ea     = (const float*)d_in[3];
    const void*  ei     = d_in[4];
    const float* W1  = (const float*)d_in[5];
    const float* b1  = (const float*)d_in[6];
    const float* g1  = (const float*)d_in[7];
    const float* be1 = (const float*)d_in[8];
    const float* W2  = (const float*)d_in[9];
    const float* b2  = (const float*)d_in[10];
    const float* g2  = (const float*)d_in[11];
    const float* be2 = (const float*)d_in[12];
    const float* Wg  = (const float*)d_in[13];
    const float* bg  = (const float*)d_in[14];
    const float* gg  = (const float*)d_in[15];
    const float* beg = (const float*)d_in[16];
    float* out = (float*)d_out;

    int E = in_sizes[4] / 2;
    int N = in_sizes[1] / 3;

    static const size_t cmpSmem = 19776 * sizeof(float);    // 79104 B
    static const size_t nodeSmem = 42752 * sizeof(float);   // 171008 B
    cudaFuncSetAttribute(compute_kernel, cudaFuncAttributeMaxDynamicSharedMemorySize,
                         (int)cmpSmem);
    cudaFuncSetAttribute(node_kernel, cudaFuncAttributeMaxDynamicSharedMemorySize,
                         (int)nodeSmem);

    init_kernel<<<64, 256>>>((const int*)ei, N);
    hist_kernel<<<512, 256>>>(ei, E);
    scan_kernel<<<1, 1024>>>(N);
    fill_kernel<<<512, 256>>>(ei, E);
    compute_kernel<<<296, 256, cmpSmem>>>(x, pos, normal, ea, ei,
                                          W1, b1, g1, be1, W2, b2, g2, be2, E, N);
    node_kernel<<<148, 512, nodeSmem>>>(Wg, bg, gg, beg, out, N);
}